// round 3
// baseline (speedup 1.0000x reference)
#include <cuda_runtime.h>
#include <cuda_bf16.h>

#define WIN 11
#define C1SSIM 1.0e-4f
#define C2SSIM 9.0e-4f

// scratch (allocation-free: __device__ globals)
__device__ float d_qn[15 * 64 * 441];   // normalized queries, [b][c][p]
__device__ float d_sn[25 * 64 * 441];   // normalized supports, [ns][c][p], ns = n*5+s
__device__ float d_mu[40 * 64 * 121];   // per image-channel gaussian mean (img 0..14 = queries, 15..39 = supports)
__device__ float d_sg[40 * 64 * 121];   // per image-channel variance (E[x^2]-mu^2)
__device__ float d_part[15 * 5 * 64];   // per (b,n,c) ssim-sum over shots and pixels

__device__ __forceinline__ void gauss(float* g) {
    float s = 0.f;
#pragma unroll
    for (int i = 0; i < WIN; i++) {
        float d = (float)i - 5.0f;
        g[i] = expf(-d * d * (1.0f / 4.5f));  // 2*sigma^2 = 4.5
        s += g[i];
    }
    float inv = 1.0f / s;
#pragma unroll
    for (int i = 0; i < WIN; i++) g[i] *= inv;
}

// K1: per-position channel L2-normalize + transpose (p,c) -> (c,p)
__global__ void k_norm(const float* __restrict__ x1, const float* __restrict__ x2) {
    int img = blockIdx.x;            // 0..39
    int p0 = blockIdx.y * 32;        // position tile
    int np = min(32, 441 - p0);
    const float* src = (img < 15) ? (x1 + img * 441 * 64) : (x2 + (img - 15) * 441 * 64);
    float* dst = (img < 15) ? (d_qn + img * 64 * 441) : (d_sn + (img - 15) * 64 * 441);

    __shared__ float t[64][33];
    __shared__ float inv[32];

    for (int i = threadIdx.x; i < np * 64; i += 256) {
        int p = i >> 6, c = i & 63;
        t[c][p] = src[(p0 + p) * 64 + c];
    }
    __syncthreads();
    if (threadIdx.x < np) {
        int p = threadIdx.x;
        float s = 0.f;
#pragma unroll
        for (int c = 0; c < 64; c++) { float v = t[c][p]; s += v * v; }
        inv[p] = rsqrtf(s);
    }
    __syncthreads();
    for (int i = threadIdx.x; i < 64 * np; i += 256) {
        int c = i / np, p = i - c * np;
        dst[c * 441 + p0 + p] = t[c][p] * inv[p];
    }
}

// K2: per (image,channel): separable 11x11 gaussian of x and x^2 -> mu, sigma^2
__global__ void k_stats() {
    int id = blockIdx.x;             // 0..2559 == img*64 + c
    int img = id >> 6, c = id & 63;
    const float* row = (img < 15) ? (d_qn + (img * 64 + c) * 441)
                                  : (d_sn + ((img - 15) * 64 + c) * 441);
    __shared__ float x[441];
    __shared__ float h1[231];
    __shared__ float h2[231];
    float g[WIN];
    gauss(g);

    for (int i = threadIdx.x; i < 441; i += 128) x[i] = row[i];
    __syncthreads();
    for (int o = threadIdx.x; o < 231; o += 128) {  // 21 rows x 11 cols
        int r = o / 11, j = o - 11 * r;
        const float* xr = x + r * 21 + j;
        float s1 = 0.f, s2 = 0.f;
#pragma unroll
        for (int k = 0; k < WIN; k++) { float v = xr[k]; s1 += g[k] * v; s2 += g[k] * v * v; }
        h1[o] = s1; h2[o] = s2;
    }
    __syncthreads();
    for (int o = threadIdx.x; o < 121; o += 128) {  // 11 x 11
        int i = o / 11, j = o - 11 * i;
        float m = 0.f, m2 = 0.f;
#pragma unroll
        for (int k = 0; k < WIN; k++) {
            m  += g[k] * h1[(i + k) * 11 + j];
            m2 += g[k] * h2[(i + k) * 11 + j];
        }
        d_mu[id * 121 + o] = m;
        d_sg[id * 121 + o] = m2 - m * m;
    }
}

__device__ __forceinline__ float block_reduce_128(float v, float* red) {
#pragma unroll
    for (int off = 16; off > 0; off >>= 1) v += __shfl_down_sync(0xffffffffu, v, off);
    int wid = threadIdx.x >> 5;
    if ((threadIdx.x & 31) == 0) red[wid] = v;
    __syncthreads();
    float r = 0.f;
    if (threadIdx.x == 0) r = red[0] + red[1] + red[2] + red[3];
    return r;
}

// K3: per (b,n,c) block, loop over 5 shots: cross-filter + ssim + reduce
__global__ void k_cross() {
    int c = blockIdx.x, n = blockIdx.y, b = blockIdx.z;
    __shared__ float q[441];
    __shared__ float z[441];
    __shared__ float h[231];
    __shared__ float red[4];
    float g[WIN];
    gauss(g);

    const float* qrow = d_qn + (b * 64 + c) * 441;
    for (int i = threadIdx.x; i < 441; i += 128) q[i] = qrow[i];
    const float* mu1p = d_mu + (b * 64 + c) * 121;
    const float* sg1p = d_sg + (b * 64 + c) * 121;

    float acc = 0.f;
    for (int s = 0; s < 5; s++) {
        int ns = n * 5 + s;
        const float* srow = d_sn + (ns * 64 + c) * 441;
        __syncthreads();  // q ready (s=0); z/h free (s>0)
        for (int i = threadIdx.x; i < 441; i += 128) z[i] = q[i] * srow[i];
        __syncthreads();
        for (int o = threadIdx.x; o < 231; o += 128) {
            int r = o / 11, j = o - 11 * r;
            const float* zr = z + r * 21 + j;
            float sv = 0.f;
#pragma unroll
            for (int k = 0; k < WIN; k++) sv += g[k] * zr[k];
            h[o] = sv;
        }
        __syncthreads();
        float val = 0.f;
        if (threadIdx.x < 121) {
            int o = threadIdx.x, i = o / 11, j = o - 11 * i;
            float t12 = 0.f;
#pragma unroll
            for (int k = 0; k < WIN; k++) t12 += g[k] * h[(i + k) * 11 + j];
            int sbase = ((15 + ns) * 64 + c) * 121 + o;
            float mu1 = mu1p[o], mu2 = d_mu[sbase];
            float sg1 = sg1p[o], sg2 = d_sg[sbase];
            float m12 = mu1 * mu2;
            float num = (2.f * m12 + C1SSIM) * (2.f * (t12 - m12) + C2SSIM);
            float den = (mu1 * mu1 + mu2 * mu2 + C1SSIM) * (sg1 + sg2 + C2SSIM);
            val = num / den;
        }
        float r = block_reduce_128(val, red);
        if (threadIdx.x == 0) acc += r;
        __syncthreads();  // red consumed before next iter
    }
    if (threadIdx.x == 0) d_part[(b * 5 + n) * 64 + c] = acc;
}

// K4: reduce channels, scale by 1/(C*H'*W')
__global__ void k_final(float* __restrict__ out) {
    int o = blockIdx.x;  // 0..74 == b*5 + n
    float v = d_part[o * 64 + threadIdx.x];
#pragma unroll
    for (int off = 16; off > 0; off >>= 1) v += __shfl_down_sync(0xffffffffu, v, off);
    __shared__ float red[2];
    if ((threadIdx.x & 31) == 0) red[threadIdx.x >> 5] = v;
    __syncthreads();
    if (threadIdx.x == 0) out[o] = (red[0] + red[1]) * (1.0f / (64.0f * 121.0f));
}

extern "C" void kernel_launch(void* const* d_in, const int* in_sizes, int n_in,
                              void* d_out, int out_size) {
    const float* x1 = (const float*)d_in[0];   // (15, 441, 64)
    const float* x2 = (const float*)d_in[1];   // (5, 5, 441, 64)
    float* out = (float*)d_out;                // (15, 5)

    dim3 g1(40, 14);
    k_norm<<<g1, 256>>>(x1, x2);
    k_stats<<<2560, 128>>>();
    dim3 g3(64, 5, 15);
    k_cross<<<g3, 128>>>();
    k_final<<<75, 64>>>(out);
}